// round 12
// baseline (speedup 1.0000x reference)
#include <cuda_runtime.h>
#include <cuda_fp16.h>
#include <math.h>

// Problem constants (fixed by the reference setup_inputs)
#define NB 256   // batches
#define NA 64    // atoms
#define NE 128   // edges per batch
#define NK 6     // neighbors per edge
#define NH 256   // hidden (fp32)
#define NH4 (NH / 4)          // 64 float4 per edge row (fp32)
#define HSPLIT 8              // CTAs per batch along H
#define NH4S (NH4 / HSPLIT)   // 8 float4 columns per edge per CTA
#define TILE (NE * NH4S)      // 1024 float4-outputs per CTA; fp16 tile = 8 KB
#define ITER (TILE / 256)     // 4 outputs per thread

__device__ __forceinline__ unsigned h2_bits(__half2 h) {
    return *reinterpret_cast<unsigned*>(&h);
}
__device__ __forceinline__ __half2 bits_h2(unsigned u) {
    return *reinterpret_cast<__half2*>(&u);
}

__global__ __launch_bounds__(256, 8)
void directed_edge_message_kernel(const float* __restrict__ rep,     // [1,B,E,H]
                                  const int*   __restrict__ pairs,   // [B,E,2]
                                  const int*   __restrict__ nbrs,    // [B,E,K]
                                  const float* __restrict__ xyz,     // [B,A,3]
                                  float*       __restrict__ out)     // [1,B,E,H]
{
    const int b   = blockIdx.x;
    const int hs  = blockIdx.y;            // 0..HSPLIT-1
    const int tid = threadIdx.x;

    __shared__ float dist_s[NE];
    __shared__ int2  pk_s[NE * NK];        // (.x = nb*NH4S, .y = half2(w,w) bits)
    __shared__ uint2 ws2[TILE];            // fp16 tile: [E][8] uint2 (64 B/edge rows)

    const float4* __restrict__ rep4 = reinterpret_cast<const float4*>(rep + (size_t)b * NE * NH);
    float4*       __restrict__ out4 = reinterpret_cast<float4*>(out + (size_t)b * NE * NH);
    const int hbase = hs * NH4S;

    // ---- Small critical-path loads first (few registers) -------------------
    int nbv[3];
    #pragma unroll
    for (int j = 0; j < 3; ++j)
        nbv[j] = nbrs[(size_t)b * NE * NK + tid + j * 256];

    float dx = 0.f, dy = 0.f, dz = 0.f;
    if (tid < NE) {
        const int base = (b * NE + tid) * 2;
        const int p0 = pairs[base + 0];
        const int p1 = pairs[base + 1];
        const float* x0 = xyz + ((size_t)b * NA + p0) * 3;
        const float* x1 = xyz + ((size_t)b * NA + p1) * 3;
        dx = x0[0] - x1[0];
        dy = x0[1] - x1[1];
        dz = x0[2] - x1[2];
    }

    // ---- Stage rep slice -> fp16 SMEM tile (LDG.128 warp = 4 edges x 128B) -
    #pragma unroll
    for (int it = 0; it < ITER; ++it) {
        const int i  = tid + it * 256;
        const int e  = i >> 3;            // / NH4S
        const int hc = i & (NH4S - 1);
        const float4 v = rep4[e * NH4 + hbase + hc];
        ws2[i] = make_uint2(h2_bits(__floats2half2_rn(v.x, v.y)),
                            h2_bits(__floats2half2_rn(v.z, v.w)));
    }

    // ---- dist --------------------------------------------------------------
    if (tid < NE) {
        const float d2 = dx * dx + dy * dy + dz * dz;
        float inv = 1.0f / d2;
        // match jnp.where(isinf(inv), 0, inv)
        dist_s[tid] = isinf(inv) ? 0.0f : inv;
    }
    __syncthreads();   // dist_s ready

    // ---- Pack (offset, half2 weight) per (edge, k) -------------------------
    #pragma unroll
    for (int j = 0; j < 3; ++j) {
        const int idx = tid + j * 256;
        const int nb  = nbv[j];
        const float w = dist_s[nb];
        pk_s[idx] = make_int2(nb * NH4S, (int)h2_bits(__floats2half2_rn(w, w)));
    }
    __syncthreads();   // ws2 + pk_s ready

    // ---- Gather: fp16 HFMA2 accumulate, convert once at writeback ----------
    #pragma unroll
    for (int it = 0; it < ITER; ++it) {
        const int i  = tid + it * 256;
        const int e  = i >> 3;
        const int hc = i & (NH4S - 1);
        const int e6 = e * NK;

        __half2 a0 = __float2half2_rn(0.f);
        __half2 a1 = a0;
        #pragma unroll
        for (int k = 0; k < NK; k++) {
            const int2    p  = pk_s[e6 + k];          // LDS.64 broadcast
            const __half2 wh = bits_h2((unsigned)p.y);
            const uint2   d  = ws2[p.x + hc];         // LDS.64, conflict-free
            a0 = __hfma2(wh, bits_h2(d.x), a0);
            a1 = __hfma2(wh, bits_h2(d.y), a1);
        }
        const float2 f0 = __half22float2(a0);
        const float2 f1 = __half22float2(a1);
        out4[e * NH4 + hbase + hc] = make_float4(f0.x, f0.y, f1.x, f1.y);
    }
}

extern "C" void kernel_launch(void* const* d_in, const int* in_sizes, int n_in,
                              void* d_out, int out_size)
{
    const float* rep   = (const float*)d_in[0];  // bond_representations [1,B,E,H]
    const int*   pairs = (const int*)  d_in[1];  // bond_pairs          [B,E,2]
    const int*   nbrs  = (const int*)  d_in[2];  // bond_neighbors      [B,E,K]
    const float* xyz   = (const float*)d_in[3];  // xyz                 [B,A,3]
    float*       out   = (float*)d_out;          // [1,B,E,H]

    dim3 grid(NB, HSPLIT);
    directed_edge_message_kernel<<<grid, 256>>>(rep, pairs, nbrs, xyz, out);
}

// round 13
// speedup vs baseline: 1.1356x; 1.1356x over previous
#include <cuda_runtime.h>
#include <cuda_fp16.h>
#include <math.h>

// Problem constants (fixed by the reference setup_inputs)
#define NB 256   // batches
#define NA 64    // atoms
#define NE 128   // edges per batch
#define NK 6     // neighbors per edge
#define NH 256   // hidden (fp32)
#define NH4 (NH / 4)          // 64 float4 per edge row (fp32)
#define HSPLIT 2              // CTAs per batch along H
#define NH4S (NH4 / HSPLIT)   // 32 float4 columns per edge per CTA
#define NW 16                 // paired-wide units per edge (uint4 = 2 float4 cols)
#define WTILE (NE * NW)       // 2048 uint4 per CTA (32 KB)
#define NT 512                // threads per CTA
#define WITER (WTILE / NT)    // 4 wide outputs per thread

__device__ __forceinline__ unsigned h2_bits(__half2 h) {
    return *reinterpret_cast<unsigned*>(&h);
}
__device__ __forceinline__ __half2 bits_h2(unsigned u) {
    return *reinterpret_cast<__half2*>(&u);
}

__global__ __launch_bounds__(NT, 4)
void directed_edge_message_kernel(const float* __restrict__ rep,     // [1,B,E,H]
                                  const int*   __restrict__ pairs,   // [B,E,2]
                                  const int*   __restrict__ nbrs,    // [B,E,K]
                                  const float* __restrict__ xyz,     // [B,A,3]
                                  float*       __restrict__ out)     // [1,B,E,H]
{
    const int b   = blockIdx.x;
    const int hs  = blockIdx.y;            // 0..HSPLIT-1
    const int tid = threadIdx.x;

    __shared__ float dist_s[NE];
    __shared__ int2  pk_s[NE * NK];        // (.x = nb*NW, .y = half2(w,w) bits)
    __shared__ uint4 ws4s[WTILE];          // paired fp16 tile: [E][16] rows of 256 B

    const float4* __restrict__ rep4 = reinterpret_cast<const float4*>(rep + (size_t)b * NE * NH);
    float4*       __restrict__ out4 = reinterpret_cast<float4*>(out + (size_t)b * NE * NH);
    const int hbase = hs * NH4S;

    // ---- Small critical-path loads first (few registers) -------------------
    int nbv[2] = {0, 0};
    nbv[0] = nbrs[(size_t)b * NE * NK + tid];
    if (tid < NE * NK - NT)
        nbv[1] = nbrs[(size_t)b * NE * NK + tid + NT];

    float dx = 0.f, dy = 0.f, dz = 0.f;
    if (tid < NE) {
        const int base = (b * NE + tid) * 2;
        const int p0 = pairs[base + 0];
        const int p1 = pairs[base + 1];
        const float* x0 = xyz + ((size_t)b * NA + p0) * 3;
        const float* x1 = xyz + ((size_t)b * NA + p1) * 3;
        dx = x0[0] - x1[0];
        dy = x0[1] - x1[1];
        dz = x0[2] - x1[2];
    }

    // ---- Stage rep slice -> paired fp16 tile (LDG->F2F->STS per iter) ------
    // ws4s[e*NW + hw] packs columns (hbase+hw) and (hbase+hw+16) of edge e.
    #pragma unroll
    for (int it = 0; it < WITER; ++it) {
        const int i  = tid + it * NT;
        const int e  = i >> 4;            // / NW
        const int hw = i & (NW - 1);
        const float4 vlo = rep4[e * NH4 + hbase + hw];
        const float4 vhi = rep4[e * NH4 + hbase + hw + NW];
        ws4s[i] = make_uint4(h2_bits(__floats2half2_rn(vlo.x, vlo.y)),
                             h2_bits(__floats2half2_rn(vlo.z, vlo.w)),
                             h2_bits(__floats2half2_rn(vhi.x, vhi.y)),
                             h2_bits(__floats2half2_rn(vhi.z, vhi.w)));
    }

    // ---- dist --------------------------------------------------------------
    if (tid < NE) {
        const float d2 = dx * dx + dy * dy + dz * dz;
        float inv = 1.0f / d2;
        // match jnp.where(isinf(inv), 0, inv)
        dist_s[tid] = isinf(inv) ? 0.0f : inv;
    }
    __syncthreads();   // dist_s ready

    // ---- Pack (offset, half2 weight) per (edge, k) -------------------------
    {
        const int nb0 = nbv[0];
        const float w0 = dist_s[nb0];
        pk_s[tid] = make_int2(nb0 * NW, (int)h2_bits(__floats2half2_rn(w0, w0)));
        if (tid < NE * NK - NT) {
            const int nb1 = nbv[1];
            const float w1 = dist_s[nb1];
            pk_s[tid + NT] = make_int2(nb1 * NW, (int)h2_bits(__floats2half2_rn(w1, w1)));
        }
    }
    __syncthreads();   // ws4s + pk_s ready

    // ---- Gather: fp16 HFMA2 accumulate, convert once at writeback ----------
    #pragma unroll
    for (int it = 0; it < WITER; ++it) {
        const int i  = tid + it * NT;
        const int e  = i >> 4;
        const int hw = i & (NW - 1);
        const int e6 = e * NK;

        __half2 a0 = __float2half2_rn(0.f);
        __half2 a1 = a0, a2 = a0, a3 = a0;
        #pragma unroll
        for (int k = 0; k < NK; k++) {
            const int2    p  = pk_s[e6 + k];          // LDS.64 broadcast (16 lanes)
            const __half2 wh = bits_h2((unsigned)p.y);
            const uint4   d  = ws4s[p.x + hw];        // LDS.128, conflict-free 256B row
            a0 = __hfma2(wh, bits_h2(d.x), a0);
            a1 = __hfma2(wh, bits_h2(d.y), a1);
            a2 = __hfma2(wh, bits_h2(d.z), a2);
            a3 = __hfma2(wh, bits_h2(d.w), a3);
        }
        const float2 f0 = __half22float2(a0);
        const float2 f1 = __half22float2(a1);
        const float2 f2 = __half22float2(a2);
        const float2 f3 = __half22float2(a3);
        out4[e * NH4 + hbase + hw]      = make_float4(f0.x, f0.y, f1.x, f1.y);
        out4[e * NH4 + hbase + hw + NW] = make_float4(f2.x, f2.y, f3.x, f3.y);
    }
}

extern "C" void kernel_launch(void* const* d_in, const int* in_sizes, int n_in,
                              void* d_out, int out_size)
{
    const float* rep   = (const float*)d_in[0];  // bond_representations [1,B,E,H]
    const int*   pairs = (const int*)  d_in[1];  // bond_pairs          [B,E,2]
    const int*   nbrs  = (const int*)  d_in[2];  // bond_neighbors      [B,E,K]
    const float* xyz   = (const float*)d_in[3];  // xyz                 [B,A,3]
    float*       out   = (float*)d_out;          // [1,B,E,H]

    dim3 grid(NB, HSPLIT);
    directed_edge_message_kernel<<<grid, NT>>>(rep, pairs, nbrs, xyz, out);
}

// round 14
// speedup vs baseline: 1.1577x; 1.0194x over previous
#include <cuda_runtime.h>
#include <cuda_fp16.h>
#include <math.h>

// Problem constants (fixed by the reference setup_inputs)
#define NB 256   // batches
#define NA 64    // atoms
#define NE 128   // edges per batch
#define NK 6     // neighbors per edge
#define NH 256   // hidden (fp32)
#define NH4 (NH / 4)          // 64 float4 per edge row (fp32)
#define NSL 8                 // h-slices per batch (8 float4 columns each)
#define SLW 8                 // slice width in float4 columns
#define TILE (NE * SLW)       // 1024 entries per slice tile
#define ITER (TILE / 256)     // 4 per thread

__device__ __forceinline__ unsigned h2_bits(__half2 h) {
    return *reinterpret_cast<unsigned*>(&h);
}
__device__ __forceinline__ __half2 bits_h2(unsigned u) {
    return *reinterpret_cast<__half2*>(&u);
}
__device__ __forceinline__ uint2 pack_f4(float4 v) {
    return make_uint2(h2_bits(__floats2half2_rn(v.x, v.y)),
                      h2_bits(__floats2half2_rn(v.z, v.w)));
}

__global__ __launch_bounds__(256, 7)
void directed_edge_message_kernel(const float* __restrict__ rep,     // [1,B,E,H]
                                  const int*   __restrict__ pairs,   // [B,E,2]
                                  const int*   __restrict__ nbrs,    // [B,E,K]
                                  const float* __restrict__ xyz,     // [B,A,3]
                                  float*       __restrict__ out)     // [1,B,E,H]
{
    const int b   = blockIdx.x;
    const int hs0 = blockIdx.y;            // this CTA does slices hs0 and hs0+4
    const int tid = threadIdx.x;

    __shared__ float dist_s[NE];
    __shared__ int2  pk_s[NE * NK];        // (.x = nb*SLW, .y = half2(w,w) bits)
    __shared__ uint2 wsA[TILE];            // fp16 slice A (8 KB)
    __shared__ uint2 wsB[TILE];            // fp16 slice B (8 KB)

    const float4* __restrict__ rep4 = reinterpret_cast<const float4*>(rep + (size_t)b * NE * NH);
    float4*       __restrict__ out4 = reinterpret_cast<float4*>(out + (size_t)b * NE * NH);
    const int hbA = hs0 * SLW;
    const int hbB = (hs0 + 4) * SLW;

    // ---- Small critical-path loads first -----------------------------------
    int nbv[3];
    #pragma unroll
    for (int j = 0; j < 3; ++j)
        nbv[j] = nbrs[(size_t)b * NE * NK + tid + j * 256];

    float dx = 0.f, dy = 0.f, dz = 0.f;
    if (tid < NE) {
        const int base = (b * NE + tid) * 2;
        const int p0 = pairs[base + 0];
        const int p1 = pairs[base + 1];
        const float* x0 = xyz + ((size_t)b * NA + p0) * 3;
        const float* x1 = xyz + ((size_t)b * NA + p1) * 3;
        dx = x0[0] - x1[0];
        dy = x0[1] - x1[1];
        dz = x0[2] - x1[2];
    }

    // ---- Stage slice A (LDG->F2F->STS, no cross-phase register arrays) -----
    #pragma unroll
    for (int it = 0; it < ITER; ++it) {
        const int i  = tid + it * 256;
        const int e  = i >> 3;            // / SLW
        const int hc = i & (SLW - 1);
        wsA[i] = pack_f4(rep4[e * NH4 + hbA + hc]);
    }

    // ---- dist ---------------------------------------------------------------
    if (tid < NE) {
        const float d2 = dx * dx + dy * dy + dz * dz;
        float inv = 1.0f / d2;
        // match jnp.where(isinf(inv), 0, inv)
        dist_s[tid] = isinf(inv) ? 0.0f : inv;
    }
    __syncthreads();   // dist_s ready

    // ---- Pack (offset, half2 weight) — shared by BOTH slices ---------------
    #pragma unroll
    for (int j = 0; j < 3; ++j) {
        const int idx = tid + j * 256;
        const int nb  = nbv[j];
        const float w = dist_s[nb];
        pk_s[idx] = make_int2(nb * SLW, (int)h2_bits(__floats2half2_rn(w, w)));
    }
    __syncthreads();   // wsA + pk_s ready

    // ---- Gather A, interleaved with stage B (LDG latency hidden) -----------
    #pragma unroll
    for (int it = 0; it < ITER; ++it) {
        const int i  = tid + it * 256;
        const int e  = i >> 3;
        const int hc = i & (SLW - 1);
        const int e6 = e * NK;

        // Issue the slice-B load for this index EARLY (independent of gather)
        const float4 vB = rep4[e * NH4 + hbB + hc];

        __half2 a0 = __float2half2_rn(0.f);
        __half2 a1 = a0;
        #pragma unroll
        for (int k = 0; k < NK; k++) {
            const int2    p  = pk_s[e6 + k];          // LDS.64 broadcast
            const __half2 wh = bits_h2((unsigned)p.y);
            const uint2   d  = wsA[p.x + hc];         // LDS.64, conflict-free
            a0 = __hfma2(wh, bits_h2(d.x), a0);
            a1 = __hfma2(wh, bits_h2(d.y), a1);
        }
        const float2 f0 = __half22float2(a0);
        const float2 f1 = __half22float2(a1);
        out4[e * NH4 + hbA + hc] = make_float4(f0.x, f0.y, f1.x, f1.y);

        // vB has had ~the whole gather iter to land; convert + store now
        wsB[i] = pack_f4(vB);
    }
    __syncthreads();   // wsB ready

    // ---- Gather B (tile already resident — zero exposed stage latency) -----
    #pragma unroll
    for (int it = 0; it < ITER; ++it) {
        const int i  = tid + it * 256;
        const int e  = i >> 3;
        const int hc = i & (SLW - 1);
        const int e6 = e * NK;

        __half2 a0 = __float2half2_rn(0.f);
        __half2 a1 = a0;
        #pragma unroll
        for (int k = 0; k < NK; k++) {
            const int2    p  = pk_s[e6 + k];
            const __half2 wh = bits_h2((unsigned)p.y);
            const uint2   d  = wsB[p.x + hc];
            a0 = __hfma2(wh, bits_h2(d.x), a0);
            a1 = __hfma2(wh, bits_h2(d.y), a1);
        }
        const float2 f0 = __half22float2(a0);
        const float2 f1 = __half22float2(a1);
        out4[e * NH4 + hbB + hc] = make_float4(f0.x, f0.y, f1.x, f1.y);
    }
}

extern "C" void kernel_launch(void* const* d_in, const int* in_sizes, int n_in,
                              void* d_out, int out_size)
{
    const float* rep   = (const float*)d_in[0];  // bond_representations [1,B,E,H]
    const int*   pairs = (const int*)  d_in[1];  // bond_pairs          [B,E,2]
    const int*   nbrs  = (const int*)  d_in[2];  // bond_neighbors      [B,E,K]
    const float* xyz   = (const float*)d_in[3];  // xyz                 [B,A,3]
    float*       out   = (float*)d_out;          // [1,B,E,H]

    dim3 grid(NB, NSL / 2);
    directed_edge_message_kernel<<<grid, 256>>>(rep, pairs, nbrs, xyz, out);
}